// round 4
// baseline (speedup 1.0000x reference)
#include <cuda_runtime.h>
#include <cuda_bf16.h>

#define NB     32
#define NZ     100
#define STATE  20
#define HIDN   128
#define HH     32
#define WW     32
#define STEPS  64
#define THRESH 0.1f

#define PIX    1024
#define IMG_SZ (STATE*PIX)
#define STATE_SZ (NB*IMG_SZ)
#define SPR    4
#define NSTRIP 128
#define TOTSTRIP 4096
#define MAXGRID 1024

// ---------------- persistent device scratch ----------------
__device__ __align__(16) float g_S[STATE_SZ];
__device__ __align__(16) float g_T[STATE_SZ];
__device__ unsigned char      g_P  [NB*PIX];
__device__ unsigned char      g_HOT[TOTSTRIP];
__device__ unsigned char      g_NZ [TOTSTRIP];
__device__ __align__(16) float g_wp_pad[60*128*4];   // [cr][hid][4] (3 used)
__device__ __align__(16) float g_wu1T  [128*128];    // [k][hid]
__device__ int                g_bar_cnt;             // zero-init, self-resetting
__device__ volatile unsigned  g_bar_gen;             // monotonic generation

// ---------------- f32x2 + cg helpers ----------------
__device__ __forceinline__ unsigned long long pack2(float v) {
    unsigned long long r; asm("mov.b64 %0, {%1, %1};" : "=l"(r) : "f"(v)); return r;
}
__device__ __forceinline__ void fma2(unsigned long long& d,
                                     unsigned long long a, unsigned long long b) {
    asm("fma.rn.f32x2 %0, %1, %2, %0;" : "+l"(d) : "l"(a), "l"(b));
}
__device__ __forceinline__ float2 unpack2(unsigned long long v) {
    float lo, hi; asm("mov.b64 {%0, %1}, %2;" : "=f"(lo), "=f"(hi) : "l"(v));
    return make_float2(lo, hi);
}
__device__ __forceinline__ unsigned ld_u8_cg(const unsigned char* p) {
    unsigned v; asm volatile("ld.global.cg.u8 %0, [%1];" : "=r"(v) : "l"(p)); return v;
}
__device__ __forceinline__ void st_u8_cg(unsigned char* p, unsigned v) {
    asm volatile("st.global.cg.u8 [%0], %1;" :: "l"(p), "r"(v));
}

// ---------------- software grid barrier ----------------
__device__ __forceinline__ void grid_barrier(int nblocks) {
    __syncthreads();
    if (threadIdx.x == 0) {
        unsigned gen = g_bar_gen;
        __threadfence();   // release: drain this CTA's .cg stores to L2
        if (atomicAdd(&g_bar_cnt, 1) == nblocks - 1) {
            g_bar_cnt = 0;
            __threadfence();
            g_bar_gen = gen + 1;
        } else {
            int spins = 0;
            while (g_bar_gen == gen) {
                if (++spins > 32) { __nanosleep(128); }
            }
        }
        asm volatile("" ::: "memory");
    }
    __syncthreads();
}

// ---------------- weight repack ----------------
__global__ void k_pack(const float* __restrict__ wp, const float* __restrict__ wu1)
{
    int i = blockIdx.x*256 + threadIdx.x;
    if (i < 128*180) {
        int h = i / 180, k = i % 180;
        g_wp_pad[(k/3)*512 + h*4 + (k%3)] = wp[i];
    }
    if (i < 128*128) {
        int h = i >> 7, k = i & 127;
        g_wu1T[k*128 + h] = wu1[i];
    }
}

// ---------------- zero state + flags ----------------
__global__ void k_zero()
{
    int i = blockIdx.x*256 + threadIdx.x;
    if (i < STATE_SZ) g_S[i] = 0.f;
    if (i < TOTSTRIP) g_NZ[i] = 0;
}

// ---------------- init MLP ----------------
__global__ void k_init(const float* __restrict__ z,
                       const float* __restrict__ w1, const float* __restrict__ b1,
                       const float* __restrict__ w2, const float* __restrict__ b2)
{
    int n = blockIdx.x;
    int t = threadIdx.x;
    __shared__ float zz[NZ];
    __shared__ float h[50];
    if (t < NZ) zz[t] = z[n*NZ + t];
    __syncthreads();
    if (t < 50) {
        float a = b1[t];
        #pragma unroll 4
        for (int j = 0; j < NZ; j++) a = fmaf(w1[t*NZ + j], zz[j], a);
        h[t] = fmaxf(a, 0.f);
    }
    __syncthreads();
    const int ctr = 16*WW + 16;
    if (t < STATE-1) {
        float a = b2[t];
        #pragma unroll 5
        for (int j = 0; j < 50; j++) a = fmaf(w2[t*50 + j], h[j], a);
        g_S[n*IMG_SZ + (1+t)*PIX + ctr] = a;
    }
    if (t == STATE-1) {
        g_S[n*IMG_SZ + ctr] = 0.5f;
        g_NZ[n*NSTRIP + 16*SPR + 2] = 1;
    }
}

// ---------------- persistent main kernel ----------------
__global__ void __launch_bounds__(128, 8)
k_main(const float* __restrict__ bp,
       const float* __restrict__ bu1,
       const float* __restrict__ wu2, const float* __restrict__ bu2,
       float* __restrict__ out)
{
    __shared__ __align__(16) float patchA[60*12];
    __shared__ __align__(16) float patchB[60*12];
    __shared__ __align__(16) float sperc[HIDN*8];
    __shared__ __align__(16) float sh2T[8*132];
    __shared__ int sflag[4];

    const int b    = blockIdx.x;
    const int G    = gridDim.x;
    const int t    = threadIdx.x;
    const int lane = t & 31;
    const int wid  = t >> 5;

    for (int step = 0; step < STEPS; step++) {

        // ================= phase A: hot test + update -> T, P, HOT =================
        int kiter = 0;
        for (int eb = b; eb < TOTSTRIP; eb += G, kiter++) {
            // transposed enumeration: image-minor for load balance
            const int n   = eb & 31;
            const int idx = eb >> 5;           // 0..127
            const int y   = idx >> 2;
            const int sx  = idx & 3;
            const int x0  = sx << 3;
            const int se  = n*NSTRIP + idx;

            // hot test: NZ dilation 5 rows x 3 strip-cols (warp 0)
            if (wid == 0) {
                int h1 = 0;
                if (lane < 15) {
                    int dy = lane/3 - 2, ds = lane%3 - 1;
                    int yy = y + dy, ss = sx + ds;
                    if ((unsigned)yy < (unsigned)HH && (unsigned)ss < (unsigned)SPR)
                        h1 = (int)ld_u8_cg(&g_NZ[n*NSTRIP + yy*SPR + ss]);
                }
                h1 = __any_sync(0xffffffffu, h1);
                if (lane == 0) {
                    sflag[kiter & 3] = h1;
                    st_u8_cg(&g_HOT[se], (unsigned)h1);
                }
            }
            __syncthreads();
            const int hot = sflag[kiter & 3];
            if (!hot) continue;

            const float* __restrict__ Sn = g_S + n*IMG_SZ;
            float* __restrict__ Tn = g_T + n*IMG_SZ;

            // ---- load patch [20][3][12] + shifted copy ----
            for (int i = t; i < 60*12; i += 128) {
                int row = i / 12, col = i - row*12;
                int c = row / 3, r = row - c*3;
                int yy = y - 1 + r, xx = x0 - 1 + col;
                float v = 0.f;
                if (col < 10 && (unsigned)yy < (unsigned)HH && (unsigned)xx < (unsigned)WW)
                    v = __ldcg(&Sn[c*PIX + yy*WW + xx]);
                patchA[i] = v;
                if (col >= 1) patchB[i - 1] = v;
                else          patchB[row*12 + 11] = 0.f;
            }
            __syncthreads();

            // ---- pre-mask ----
            if (t < 8) {
                float m = 0.f;
                #pragma unroll
                for (int r = 0; r < 3; r++)
                    #pragma unroll
                    for (int cc = 0; cc < 3; cc++)
                        m = fmaxf(m, patchA[r*12 + t + cc]);
                st_u8_cg(&g_P[n*PIX + y*WW + x0 + t], (m > THRESH) ? 1u : 0u);
            }

            // ---- perceive: 3x3 conv 20->128 (f32x2, pixel pairs) ----
            unsigned long long acc[4];
            {
                unsigned long long b2v = pack2(__ldg(&bp[t]));
                acc[0] = b2v; acc[1] = b2v; acc[2] = b2v; acc[3] = b2v;
            }
            #pragma unroll 2
            for (int cr = 0; cr < 60; cr++) {
                const ulonglong2 pa0 = *(const ulonglong2*)&patchA[cr*12 + 0];
                const ulonglong2 pa1 = *(const ulonglong2*)&patchA[cr*12 + 4];
                const unsigned long long d8 = *(const unsigned long long*)&patchA[cr*12 + 8];
                const ulonglong2 pb0 = *(const ulonglong2*)&patchB[cr*12 + 0];
                const ulonglong2 pb1 = *(const ulonglong2*)&patchB[cr*12 + 4];
                const float4 w4 = __ldg((const float4*)&g_wp_pad[(cr*128 + t)*4]);
                const unsigned long long W0 = pack2(w4.x);
                const unsigned long long W1 = pack2(w4.y);
                const unsigned long long W2 = pack2(w4.z);
                fma2(acc[0], W0, pa0.x); fma2(acc[1], W0, pa0.y);
                fma2(acc[2], W0, pa1.x); fma2(acc[3], W0, pa1.y);
                fma2(acc[0], W1, pb0.x); fma2(acc[1], W1, pb0.y);
                fma2(acc[2], W1, pb1.x); fma2(acc[3], W1, pb1.y);
                fma2(acc[0], W2, pa0.y); fma2(acc[1], W2, pa1.x);
                fma2(acc[2], W2, pa1.y); fma2(acc[3], W2, d8);
            }
            {
                unsigned long long* sp = (unsigned long long*)sperc;
                sp[t*4 + 0] = acc[0]; sp[t*4 + 1] = acc[1];
                sp[t*4 + 2] = acc[2]; sp[t*4 + 3] = acc[3];
            }
            __syncthreads();

            // ---- up1: 1x1 128->128 + relu ----
            unsigned long long acc2[4];
            {
                unsigned long long b2v = pack2(__ldg(&bu1[t]));
                acc2[0] = b2v; acc2[1] = b2v; acc2[2] = b2v; acc2[3] = b2v;
            }
            #pragma unroll 4
            for (int k = 0; k < 128; k++) {
                const ulonglong2 v0 = *(const ulonglong2*)&sperc[k*8 + 0];
                const ulonglong2 v1 = *(const ulonglong2*)&sperc[k*8 + 4];
                const unsigned long long W = pack2(__ldg(&g_wu1T[k*128 + t]));
                fma2(acc2[0], W, v0.x); fma2(acc2[1], W, v0.y);
                fma2(acc2[2], W, v1.x); fma2(acc2[3], W, v1.y);
            }
            #pragma unroll
            for (int j = 0; j < 4; j++) {
                float2 v = unpack2(acc2[j]);
                sh2T[(2*j+0)*132 + t] = fmaxf(v.x, 0.f);
                sh2T[(2*j+1)*132 + t] = fmaxf(v.y, 0.f);
            }
            __syncthreads();

            // ---- up2: 1x1 128->20, T = S + upd ----
            #pragma unroll
            for (int round = 0; round < 2; round++) {
                int i2 = t + round*128;
                if (i2 < 160) {
                    int c = i2 >> 3, p = i2 & 7;
                    unsigned long long A0 = 0ull, A1 = 0ull;
                    const ulonglong2* hv = (const ulonglong2*)&sh2T[p*132];
                    const ulonglong2* wv = (const ulonglong2*)&wu2[c*128];
                    #pragma unroll 8
                    for (int k4 = 0; k4 < 32; k4++) {
                        const ulonglong2 h2 = hv[k4];
                        const ulonglong2 w2 = __ldg(&wv[k4]);
                        fma2(A0, w2.x, h2.x);
                        fma2(A1, w2.y, h2.y);
                    }
                    float2 s0 = unpack2(A0), s1 = unpack2(A1);
                    float a = __ldg(&bu2[c]) + ((s0.x + s0.y) + (s1.x + s1.y));
                    __stcg(&Tn[c*PIX + y*WW + x0 + p],
                           patchA[(c*3+1)*12 + p + 1] + a);
                }
            }
            __syncthreads();
        }

        grid_barrier(G);

        // ================= phase B: post maxpool + masking -> S, NZ =================
        for (int ww = b*4 + wid; ww < TOTSTRIP; ww += G*4) {
            const int n   = ww & 31;
            const int idx = ww >> 5;
            const int y   = idx >> 2;
            const int x0  = (idx & 3) << 3;
            const int se  = n*NSTRIP + idx;

            unsigned hot = ld_u8_cg(&g_HOT[se]);
            unsigned nz  = ld_u8_cg(&g_NZ[se]);
            if (!(hot | nz)) continue;

            const int q   = lane >> 2;      // pixel within strip
            const int cgp = lane & 3;       // channel group (5 ch each)
            const int x   = x0 + q;
            const int px  = y*WW + x;
            const float* __restrict__ Tn = g_T + n*IMG_SZ;
            float* __restrict__ Sn = g_S + n*IMG_SZ;

            int alive = 0;
            if (hot && cgp == 0) {
                if (ld_u8_cg(&g_P[n*PIX + px])) {
                    float m = -1.f;
                    #pragma unroll
                    for (int dy = -1; dy <= 1; dy++) {
                        int yy = y + dy;
                        if ((unsigned)yy >= (unsigned)HH) continue;
                        #pragma unroll
                        for (int dx = -1; dx <= 1; dx++) {
                            int xx = x + dx;
                            if ((unsigned)xx >= (unsigned)WW) continue;
                            m = fmaxf(m, __ldcg(&Tn[yy*WW + xx]));
                        }
                    }
                    alive = (m > THRESH) ? 1 : 0;
                }
            }
            alive = __shfl_sync(0xffffffffu, alive, lane & ~3);
            unsigned bal = __ballot_sync(0xffffffffu, alive);

            if (hot) {
                #pragma unroll
                for (int i = 0; i < 5; i++) {
                    int c = cgp*5 + i;
                    float v = alive ? __ldcg(&Tn[c*PIX + px]) : 0.f;
                    __stcg(&Sn[c*PIX + px], v);
                }
                if (lane == 0) st_u8_cg(&g_NZ[se], bal ? 1u : 0u);
            } else {
                #pragma unroll
                for (int i = 0; i < 5; i++)
                    __stcg(&Sn[(cgp*5 + i)*PIX + px], 0.f);
                if (lane == 0) st_u8_cg(&g_NZ[se], 0u);
            }
        }

        grid_barrier(G);
    }

    // ---- extract ch0 (each CTA strided over 32768 pixels) ----
    for (int gg = b*32 + t; gg < NB*PIX; gg += G*128) {
        int n = gg >> 10, rem = gg & 1023;
        out[gg] = __ldcg(&g_S[n*IMG_SZ + rem]);
    }
}

// ---------------- launch ----------------
extern "C" void kernel_launch(void* const* d_in, const int* in_sizes, int n_in,
                              void* d_out, int out_size)
{
    const float* z   = (const float*)d_in[0];
    const float* w1  = (const float*)d_in[1];
    const float* b1  = (const float*)d_in[2];
    const float* w2  = (const float*)d_in[3];
    const float* b2  = (const float*)d_in[4];
    const float* wp  = (const float*)d_in[5];
    const float* bp  = (const float*)d_in[6];
    const float* wu1 = (const float*)d_in[7];
    const float* bu1 = (const float*)d_in[8];
    const float* wu2 = (const float*)d_in[9];
    const float* bu2 = (const float*)d_in[10];
    float* out = (float*)d_out;

    // deterministic co-residency bound (host API, capture-safe, no allocs)
    int smCount = 0, blocksPerSM = 0;
    cudaDeviceGetAttribute(&smCount, cudaDevAttrMultiProcessorCount, 0);
    cudaOccupancyMaxActiveBlocksPerMultiprocessor(&blocksPerSM, k_main, 128, 0);
    int grid = smCount * blocksPerSM;
    if (grid > MAXGRID) grid = MAXGRID;
    if (grid < 1) grid = 1;

    k_pack<<<(128*180 + 255)/256, 256>>>(wp, wu1);
    k_zero<<<(STATE_SZ + 255)/256, 256>>>();
    k_init<<<NB, 128>>>(z, w1, b1, w2, b2);
    k_main<<<grid, 128>>>(bp, bu1, wu2, bu2, out);
}

// round 5
// speedup vs baseline: 1.2050x; 1.2050x over previous
#include <cuda_runtime.h>
#include <cuda_bf16.h>

#define NB     32
#define NZ     100
#define STATE  20
#define HIDN   128
#define HH     32
#define WW     32
#define STEPS  64
#define THRESH 0.1f

#define PIX    1024
#define IMG_SZ (STATE*PIX)
#define STATE_SZ (NB*IMG_SZ)
#define SPR    4
#define NSTRIP 128
#define TOTSTRIP 4096

// ---------------- persistent device scratch ----------------
__device__ __align__(16) float g_S[STATE_SZ];
__device__ __align__(16) float g_T[STATE_SZ];
__device__ unsigned char      g_P  [NB*PIX];
__device__ unsigned char      g_HOT[TOTSTRIP];
__device__ unsigned char      g_NZ [TOTSTRIP];
__device__ __align__(16) float g_wp_pad[60*128*4];   // [cr][hid][4] (3 used)
__device__ __align__(16) float g_wu1T  [128*128];    // [k][hid]

// ---------------- f32x2 helpers ----------------
__device__ __forceinline__ unsigned long long pack2(float v) {
    unsigned long long r; asm("mov.b64 %0, {%1, %1};" : "=l"(r) : "f"(v)); return r;
}
__device__ __forceinline__ void fma2(unsigned long long& d,
                                     unsigned long long a, unsigned long long b) {
    asm("fma.rn.f32x2 %0, %1, %2, %0;" : "+l"(d) : "l"(a), "l"(b));
}
__device__ __forceinline__ float2 unpack2(unsigned long long v) {
    float lo, hi; asm("mov.b64 {%0, %1}, %2;" : "=f"(lo), "=f"(hi) : "l"(v));
    return make_float2(lo, hi);
}

// ---------------- weight repack ----------------
__global__ void k_pack(const float* __restrict__ wp, const float* __restrict__ wu1)
{
    int i = blockIdx.x*256 + threadIdx.x;
    if (i < 128*180) {
        int h = i / 180, k = i % 180;
        g_wp_pad[(k/3)*512 + h*4 + (k%3)] = wp[i];
    }
    if (i < 128*128) {
        int h = i >> 7, k = i & 127;
        g_wu1T[k*128 + h] = wu1[i];
    }
}

// ---------------- zero state + flags ----------------
__global__ void k_zero()
{
    int i = blockIdx.x*256 + threadIdx.x;
    if (i < STATE_SZ) g_S[i] = 0.f;
    if (i < TOTSTRIP) g_NZ[i] = 0;
}

// ---------------- init MLP ----------------
__global__ void k_init(const float* __restrict__ z,
                       const float* __restrict__ w1, const float* __restrict__ b1,
                       const float* __restrict__ w2, const float* __restrict__ b2)
{
    int n = blockIdx.x;
    int t = threadIdx.x;
    __shared__ float zz[NZ];
    __shared__ float h[50];
    if (t < NZ) zz[t] = z[n*NZ + t];
    __syncthreads();
    if (t < 50) {
        float a = b1[t];
        #pragma unroll 4
        for (int j = 0; j < NZ; j++) a = fmaf(w1[t*NZ + j], zz[j], a);
        h[t] = fmaxf(a, 0.f);
    }
    __syncthreads();
    const int ctr = 16*WW + 16;
    if (t < STATE-1) {
        float a = b2[t];
        #pragma unroll 5
        for (int j = 0; j < 50; j++) a = fmaf(w2[t*50 + j], h[j], a);
        g_S[n*IMG_SZ + (1+t)*PIX + ctr] = a;
    }
    if (t == STATE-1) {
        g_S[n*IMG_SZ + ctr] = 0.5f;
        g_NZ[n*NSTRIP + 16*SPR + 2] = 1;
    }
}

// ---------------- step kernel 1: one CTA per strip, 256 threads ----------------
// thread t: h = t&127 (hid channel), ph = t>>7 (pixel half: 0 -> px 0-3, 1 -> px 4-7)
__global__ void __launch_bounds__(256)
k_step1(const float* __restrict__ bp,
        const float* __restrict__ bu1,
        const float* __restrict__ wu2, const float* __restrict__ bu2)
{
    __shared__ __align__(16) float patchA[60*12];
    __shared__ __align__(16) float patchB[60*12];
    __shared__ __align__(16) float sperc[HIDN*8];   // [hid][8]
    __shared__ __align__(16) float sh2T[8*132];     // [p][132]
    __shared__ int sflag;

    const int e   = blockIdx.x;            // 0..4095
    const int n   = e & 31;                // transposed: image-minor
    const int idx = e >> 5;                // 0..127
    const int y   = idx >> 2;
    const int sx  = idx & 3;
    const int x0  = sx << 3;
    const int se  = n*NSTRIP + idx;
    const int t   = threadIdx.x;
    const int lane = t & 31;

    // ---- hot test: dilate NZ by 5 rows x 3 strip-cols ----
    if (t < 32) {
        int h1 = 0;
        if (lane < 15) {
            int dy = lane/3 - 2, ds = lane%3 - 1;
            int yy = y + dy, ss = sx + ds;
            if ((unsigned)yy < (unsigned)HH && (unsigned)ss < (unsigned)SPR)
                h1 = g_NZ[n*NSTRIP + yy*SPR + ss];
        }
        h1 = __any_sync(0xffffffffu, h1);
        if (lane == 0) {
            sflag = h1;
            g_HOT[se] = (unsigned char)h1;
        }
    }
    __syncthreads();
    if (!sflag) return;

    const float* __restrict__ Sn = g_S + n*IMG_SZ;
    float* __restrict__ Tn = g_T + n*IMG_SZ;

    // ---- load patch [20][3][12] + shifted copy ----
    for (int i = t; i < 60*12; i += 256) {
        int row = i / 12, col = i - row*12;
        int c = row / 3, r = row - c*3;
        int yy = y - 1 + r, xx = x0 - 1 + col;
        float v = 0.f;
        if (col < 10 && (unsigned)yy < (unsigned)HH && (unsigned)xx < (unsigned)WW)
            v = Sn[c*PIX + yy*WW + xx];
        patchA[i] = v;
        if (col >= 1) patchB[i - 1] = v;
        else          patchB[row*12 + 11] = 0.f;
    }
    __syncthreads();

    // ---- pre-mask for 8 strip pixels ----
    if (t < 8) {
        float m = 0.f;
        #pragma unroll
        for (int r = 0; r < 3; r++)
            #pragma unroll
            for (int cc = 0; cc < 3; cc++)
                m = fmaxf(m, patchA[r*12 + t + cc]);
        g_P[n*PIX + y*WW + x0 + t] = (m > THRESH) ? 1 : 0;
    }

    const int h  = t & 127;
    const int ph = t >> 7;        // 0 or 1
    const int pb4 = ph * 4;       // pixel base

    // ---- perceive: 3x3 conv 20->128, 4 pixels (2 f32x2 accs) per thread ----
    unsigned long long acc0, acc1;
    {
        unsigned long long b2v = pack2(__ldg(&bp[h]));
        acc0 = b2v; acc1 = b2v;
    }
    #pragma unroll 4
    for (int cr = 0; cr < 60; cr++) {
        const ulonglong2 pa = *(const ulonglong2*)&patchA[cr*12 + pb4];
        const ulonglong2 pbv = *(const ulonglong2*)&patchB[cr*12 + pb4];
        const unsigned long long pc = *(const unsigned long long*)&patchA[cr*12 + pb4 + 4];
        const float4 w4 = __ldg((const float4*)&g_wp_pad[(cr*128 + h)*4]);
        const unsigned long long W0 = pack2(w4.x);
        const unsigned long long W1 = pack2(w4.y);
        const unsigned long long W2 = pack2(w4.z);
        fma2(acc0, W0, pa.x);  fma2(acc1, W0, pa.y);
        fma2(acc0, W1, pbv.x); fma2(acc1, W1, pbv.y);
        fma2(acc0, W2, pa.y);  fma2(acc1, W2, pc);
    }
    {
        unsigned long long* sp = (unsigned long long*)sperc;
        sp[h*4 + ph*2 + 0] = acc0;
        sp[h*4 + ph*2 + 1] = acc1;
    }
    __syncthreads();

    // ---- up1: 1x1 128->128 + relu ----
    unsigned long long acc2_0, acc2_1;
    {
        unsigned long long b2v = pack2(__ldg(&bu1[h]));
        acc2_0 = b2v; acc2_1 = b2v;
    }
    #pragma unroll 8
    for (int k = 0; k < 128; k++) {
        const ulonglong2 v = *(const ulonglong2*)&sperc[k*8 + pb4];
        const unsigned long long W = pack2(__ldg(&g_wu1T[k*128 + h]));
        fma2(acc2_0, W, v.x);
        fma2(acc2_1, W, v.y);
    }
    {
        float2 v0 = unpack2(acc2_0), v1 = unpack2(acc2_1);
        sh2T[(pb4+0)*132 + h] = fmaxf(v0.x, 0.f);
        sh2T[(pb4+1)*132 + h] = fmaxf(v0.y, 0.f);
        sh2T[(pb4+2)*132 + h] = fmaxf(v1.x, 0.f);
        sh2T[(pb4+3)*132 + h] = fmaxf(v1.y, 0.f);
    }
    __syncthreads();

    // ---- up2: 1x1 128->20, T = S + upd (160 outputs) ----
    if (t < 160) {
        int c = t >> 3, p = t & 7;
        unsigned long long A0 = 0ull, A1 = 0ull;
        const ulonglong2* hv = (const ulonglong2*)&sh2T[p*132];
        const ulonglong2* wv = (const ulonglong2*)&wu2[c*128];
        #pragma unroll 8
        for (int k4 = 0; k4 < 32; k4++) {
            const ulonglong2 h2 = hv[k4];
            const ulonglong2 w2 = __ldg(&wv[k4]);
            fma2(A0, w2.x, h2.x);
            fma2(A1, w2.y, h2.y);
        }
        float2 s0 = unpack2(A0), s1 = unpack2(A1);
        float a = __ldg(&bu2[c]) + ((s0.x + s0.y) + (s1.x + s1.y));
        Tn[c*PIX + y*WW + x0 + p] = patchA[(c*3+1)*12 + p + 1] + a;
    }
}

// ---------------- step kernel 2: warp per strip, post maxpool + masking ----------------
__global__ void __launch_bounds__(256)
k_step2()
{
    const int wid  = threadIdx.x >> 5;
    const int lane = threadIdx.x & 31;
    const int ww   = blockIdx.x*8 + wid;       // strip id 0..4095
    const int n    = ww & 31;
    const int idx  = ww >> 5;
    const int y    = idx >> 2;
    const int x0   = (idx & 3) << 3;
    const int se   = n*NSTRIP + idx;

    unsigned char hot = g_HOT[se];
    unsigned char nz  = g_NZ[se];
    if (!(hot | nz)) return;

    const int q   = lane >> 2;       // pixel 0..7
    const int cgp = lane & 3;        // channel group (5 ch each)
    const int x   = x0 + q;
    const int px  = y*WW + x;
    const float* __restrict__ Tn = g_T + n*IMG_SZ;
    float* __restrict__ Sn = g_S + n*IMG_SZ;

    int alive = 0;
    if (hot && cgp == 0) {
        if (g_P[n*PIX + px]) {
            float m = -1.f;
            #pragma unroll
            for (int dy = -1; dy <= 1; dy++) {
                int yy = y + dy;
                if ((unsigned)yy >= (unsigned)HH) continue;
                #pragma unroll
                for (int dx = -1; dx <= 1; dx++) {
                    int xx = x + dx;
                    if ((unsigned)xx >= (unsigned)WW) continue;
                    m = fmaxf(m, Tn[yy*WW + xx]);
                }
            }
            alive = (m > THRESH) ? 1 : 0;
        }
    }
    alive = __shfl_sync(0xffffffffu, alive, lane & ~3);
    unsigned bal = __ballot_sync(0xffffffffu, alive);

    if (hot) {
        #pragma unroll
        for (int i = 0; i < 5; i++) {
            int c = cgp*5 + i;
            Sn[c*PIX + px] = alive ? Tn[c*PIX + px] : 0.f;
        }
        if (lane == 0) g_NZ[se] = bal ? 1 : 0;
    } else {
        #pragma unroll
        for (int i = 0; i < 5; i++)
            Sn[(cgp*5 + i)*PIX + px] = 0.f;
        if (lane == 0) g_NZ[se] = 0;
    }
}

// ---------------- extract output ----------------
__global__ void k_extract(float* __restrict__ out)
{
    int g = blockIdx.x*256 + threadIdx.x;
    int n = g >> 10, rem = g & 1023;
    out[g] = g_S[n*IMG_SZ + rem];
}

// ---------------- launch ----------------
extern "C" void kernel_launch(void* const* d_in, const int* in_sizes, int n_in,
                              void* d_out, int out_size)
{
    const float* z   = (const float*)d_in[0];
    const float* w1  = (const float*)d_in[1];
    const float* b1  = (const float*)d_in[2];
    const float* w2  = (const float*)d_in[3];
    const float* b2  = (const float*)d_in[4];
    const float* wp  = (const float*)d_in[5];
    const float* bp  = (const float*)d_in[6];
    const float* wu1 = (const float*)d_in[7];
    const float* bu1 = (const float*)d_in[8];
    const float* wu2 = (const float*)d_in[9];
    const float* bu2 = (const float*)d_in[10];
    float* out = (float*)d_out;

    k_pack<<<(128*180 + 255)/256, 256>>>(wp, wu1);
    k_zero<<<(STATE_SZ + 255)/256, 256>>>();
    k_init<<<NB, 128>>>(z, w1, b1, w2, b2);

    for (int s = 0; s < STEPS; s++) {
        k_step1<<<TOTSTRIP, 256>>>(bp, bu1, wu2, bu2);
        k_step2<<<TOTSTRIP/8, 256>>>();
    }
    k_extract<<<(NB*PIX)/256, 256>>>(out);
}